// round 5
// baseline (speedup 1.0000x reference)
#include <cuda_runtime.h>
#include <cuda_fp16.h>
#include <cstdint>
#include <cstddef>

// Problem constants: N=100000, E=1600000, F=128, H=64, C=40, G=2048
#define NMAX 100000
#define EMAX 1600000
#define GMAX 2048

// ---------------- scratch (device globals; no runtime alloc allowed) ----------------
__device__ __align__(16) float  g_h  [NMAX * 64];   // pre-MLP output (fp32)
__device__ __align__(16) __half g_hws[NMAX * 64];   // (h @ W) * isq (fp16) per layer
__device__ __align__(16) float  g_h1 [NMAX * 64];   // layer-1 activations (for skip)
__device__ __align__(16) float  g_deg[NMAX];        // isq
__device__ __align__(16) float  g_readout[GMAX * 64];
__device__ __align__(16) int    g_cnt[NMAX];        // per-dst degree
__device__ __align__(16) int    g_ptr[NMAX];        // CSR row starts
__device__ __align__(16) int    g_cursor[NMAX];     // fill cursors
__device__ __align__(16) int    g_csr_src[EMAX];    // CSR column (src) indices
__device__ int g_scanflag[128];                     // lookback published aggregates (+1)
__device__ unsigned g_bar_cnt;                      // grid barrier arrivals
__device__ unsigned g_bar_gen;                      // grid barrier generation

// ---------------- grid barrier (single-wave persistent grid only) ----------------
__device__ __forceinline__ void grid_barrier() {
    __syncthreads();
    if (threadIdx.x == 0) {
        __threadfence();
        unsigned gen = atomicAdd(&g_bar_gen, 0u);
        unsigned prev = atomicAdd(&g_bar_cnt, 1u);
        if (prev == gridDim.x - 1) {
            atomicExch(&g_bar_cnt, 0u);
            __threadfence();
            atomicAdd(&g_bar_gen, 1u);
        } else {
            while (atomicAdd(&g_bar_gen, 0u) == gen) {}
        }
    }
    __syncthreads();
}

// ---------------- per-block index-dtype detection ----------------
// Random src values in [0,N) read as int64 pairs give huge values -> detect int32.
__device__ __forceinline__ int block_detect_idx32(const void* e, int E, long long nlim,
                                                  int* s_flag) {
    if (threadIdx.x == 0) *s_flag = 0;
    __syncthreads();
    int m = E < 64 ? E : 64;
    if ((int)threadIdx.x < m) {
        long long v = ((const long long*)e)[threadIdx.x];
        if (v < 0 || v >= nlim) *s_flag = 1;
    }
    __syncthreads();
    return *s_flag;
}

// ---------------- fused CSR build: hist -> scan(+isq) -> fill, one persistent kernel --
__global__ void __launch_bounds__(256) k_csr(const void* __restrict__ eidx, int E, int n) {
    __shared__ int sf;
    int idx32 = block_detect_idx32(eidx, E, (long long)n, &sf);
    int gtid = blockIdx.x * blockDim.x + threadIdx.x;
    int gstride = gridDim.x * blockDim.x;

    // ---- phase 1: degree histogram (grid-stride, 4 edges/iter) ----
    if (idx32) {
        const int* d = (const int*)eidx + E;
        for (int b = gtid * 4; b < E; b += gstride * 4) {
#pragma unroll
            for (int k = 0; k < 4; k++)
                if (b + k < E) atomicAdd(&g_cnt[d[b + k]], 1);
        }
    } else {
        const long long* d = (const long long*)eidx + E;
        for (int b = gtid * 4; b < E; b += gstride * 4) {
#pragma unroll
            for (int k = 0; k < 4; k++)
                if (b + k < E) atomicAdd(&g_cnt[(int)d[b + k]], 1);
        }
    }
    grid_barrier();

    // ---- phase 2: exclusive scan over tiles of 1024 (blocks 0..ntiles-1), + isq ----
    int ntiles = (n + 1023) / 1024;   // <= 98 <= gridDim.x
    if (blockIdx.x < (unsigned)ntiles) {
        __shared__ int wsum[8];
        __shared__ int red[8];
        __shared__ int s_prefix;
        int bid = blockIdx.x;
        int base = bid * 1024 + threadIdx.x * 4;

        int c0 = 0, c1 = 0, c2 = 0, c3 = 0;
        if (base + 3 < n) {
            int4 c = *(const int4*)&g_cnt[base];
            c0 = c.x; c1 = c.y; c2 = c.z; c3 = c.w;
        } else if (base < n) {
            c0 = g_cnt[base];
            if (base + 1 < n) c1 = g_cnt[base + 1];
            if (base + 2 < n) c2 = g_cnt[base + 2];
        }
        int tot = c0 + c1 + c2 + c3;
        int lane = threadIdx.x & 31, wid = threadIdx.x >> 5;
        int v = tot;
#pragma unroll
        for (int o = 1; o < 32; o <<= 1) {
            int u = __shfl_up_sync(0xffffffffu, v, o);
            if (lane >= o) v += u;
        }
        if (lane == 31) wsum[wid] = v;
        __syncthreads();
        if (threadIdx.x == 0) {
            int s = 0;
            for (int i = 0; i < 8; i++) { int t = wsum[i]; wsum[i] = s; s += t; }
            atomicExch(&g_scanflag[bid], s + 1);   // publish aggregate (+1 = ready)
        }
        __syncthreads();

        int part = 0;
        if ((int)threadIdx.x < bid) {
            volatile int* f = &g_scanflag[threadIdx.x];
            int x;
            do { x = *f; } while (x == 0);
            part = x - 1;
        }
#pragma unroll
        for (int o = 16; o; o >>= 1) part += __shfl_xor_sync(0xffffffffu, part, o);
        if (lane == 0) red[wid] = part;
        __syncthreads();
        if (threadIdx.x == 0) {
            int s = 0;
            for (int i = 0; i < 8; i++) s += red[i];
            s_prefix = s;
        }
        __syncthreads();

        int excl = v - tot + wsum[wid] + s_prefix;
        if (base < n) {
            int p0 = excl, p1 = p0 + c0, p2 = p1 + c1, p3 = p2 + c2;
            g_ptr[base] = p0; g_cursor[base] = p0; g_deg[base] = rsqrtf((float)c0 + 1.0f);
            if (base + 1 < n) { g_ptr[base+1] = p1; g_cursor[base+1] = p1; g_deg[base+1] = rsqrtf((float)c1 + 1.0f); }
            if (base + 2 < n) { g_ptr[base+2] = p2; g_cursor[base+2] = p2; g_deg[base+2] = rsqrtf((float)c2 + 1.0f); }
            if (base + 3 < n) { g_ptr[base+3] = p3; g_cursor[base+3] = p3; g_deg[base+3] = rsqrtf((float)c3 + 1.0f); }
        }
    }
    grid_barrier();

    // ---- phase 3: CSR fill (grid-stride, 4 edges/iter) ----
    for (int b = gtid * 4; b < E; b += gstride * 4) {
#pragma unroll
        for (int k = 0; k < 4; k++) {
            int e = b + k;
            if (e >= E) break;
            int src, dst;
            if (idx32) {
                const int* p = (const int*)eidx;
                src = p[e]; dst = p[E + e];
            } else {
                const long long* p = (const long long*)eidx;
                src = (int)p[e]; dst = (int)p[E + e];
            }
            int pos = atomicAdd(&g_cursor[dst], 1);
            g_csr_src[pos] = src;
        }
    }
}

// ---------------- row GEMM, packed f32x2 FMA; fp32+bias OR fp16*(isq) output ---------
template<int K, int HALF_OUT>
__global__ void __launch_bounds__(128) k_gemm(const float* __restrict__ A,
                                              const float* __restrict__ W,
                                              const float* __restrict__ bias,
                                              const float* __restrict__ isq,
                                              void* __restrict__ out, int n) {
    __shared__ ulonglong2 Ws[K * 16];   // K rows x 64 floats, pre-packed f32x2 pairs
    __shared__ float      As[128 * 17];

    for (int i = threadIdx.x; i < K * 16; i += 128)
        Ws[i] = reinterpret_cast<const ulonglong2*>(W)[i];

    unsigned long long acc[32];
#pragma unroll
    for (int j = 0; j < 32; j++) acc[j] = 0ULL;

    int node = blockIdx.x * 128 + threadIdx.x;

    for (int k0 = 0; k0 < K; k0 += 16) {
        __syncthreads();
#pragma unroll
        for (int i = 0; i < 16; i++) {
            int idx = i * 128 + threadIdx.x;
            int nn = idx >> 4, kk = idx & 15;
            int gn = blockIdx.x * 128 + nn;
            As[nn * 17 + kk] = (gn < n) ? A[(size_t)gn * K + k0 + kk] : 0.f;
        }
        __syncthreads();
#pragma unroll
        for (int kk = 0; kk < 16; kk++) {
            float a = As[threadIdx.x * 17 + kk];
            unsigned long long a2;
            asm("mov.b64 %0, {%1, %1};" : "=l"(a2) : "f"(a));
            const ulonglong2* wr = &Ws[(k0 + kk) * 16];
#pragma unroll
            for (int j = 0; j < 16; j++) {
                ulonglong2 w = wr[j];
                asm("fma.rn.f32x2 %0, %1, %2, %0;" : "+l"(acc[2 * j])     : "l"(a2), "l"(w.x));
                asm("fma.rn.f32x2 %0, %1, %2, %0;" : "+l"(acc[2 * j + 1]) : "l"(a2), "l"(w.y));
            }
        }
    }

    if (node < n) {
        if (HALF_OUT) {
            float s = isq[node];
            __half2* o = reinterpret_cast<__half2*>(out) + (size_t)node * 32;
#pragma unroll
            for (int j = 0; j < 32; j++) {
                float lo, hi;
                asm("mov.b64 {%0, %1}, %2;" : "=f"(lo), "=f"(hi) : "l"(acc[j]));
                o[j] = __floats2half2_rn(lo * s, hi * s);
            }
        } else {
            float2* o = reinterpret_cast<float2*>(out) + (size_t)node * 32;
#pragma unroll
            for (int j = 0; j < 32; j++) {
                float lo, hi;
                asm("mov.b64 {%0, %1}, %2;" : "=f"(lo), "=f"(hi) : "l"(acc[j]));
                float2 b = reinterpret_cast<const float2*>(bias)[j];
                o[j] = make_float2(lo + b.x, hi + b.y);
            }
        }
    }
}

// ---------------- fused gather + self + bias + LN + ReLU (+skip+readout) -------------
// One warp per node; hws rows are fp16 (exactly one 128B line per neighbor).
__global__ void __launch_bounds__(256) k_gather(const float* __restrict__ bias,
                                                const float* __restrict__ lng,
                                                const float* __restrict__ lnb,
                                                float* __restrict__ outh, int n,
                                                int do_readout,
                                                const void* __restrict__ batch,
                                                const void* __restrict__ eidx, int E) {
    __shared__ int sf;
    int idx32 = block_detect_idx32(eidx, E, (long long)n, &sf);

    int t = blockIdx.x * blockDim.x + threadIdx.x;
    int node = t >> 5, lane = t & 31;
    if (node >= n) return;

    int start = g_ptr[node];
    int cnt   = g_cnt[node];
    const __half2* hw = (const __half2*)g_hws;
    size_t off = (size_t)node * 32 + lane;

    float2 self = __half22float2(__ldg(&hw[off]));   // already scaled by isq
    float ax0 = self.x, ay0 = self.y;
    float ax1 = 0.f, ay1 = 0.f, ax2 = 0.f, ay2 = 0.f, ax3 = 0.f, ay3 = 0.f;

    int j = 0;
    for (; j + 3 < cnt; j += 4) {
        int s0 = __ldg(&g_csr_src[start + j]);
        int s1 = __ldg(&g_csr_src[start + j + 1]);
        int s2 = __ldg(&g_csr_src[start + j + 2]);
        int s3 = __ldg(&g_csr_src[start + j + 3]);
        float2 v0 = __half22float2(__ldg(&hw[(size_t)s0 * 32 + lane]));
        float2 v1 = __half22float2(__ldg(&hw[(size_t)s1 * 32 + lane]));
        float2 v2 = __half22float2(__ldg(&hw[(size_t)s2 * 32 + lane]));
        float2 v3 = __half22float2(__ldg(&hw[(size_t)s3 * 32 + lane]));
        ax0 += v0.x; ay0 += v0.y;
        ax1 += v1.x; ay1 += v1.y;
        ax2 += v2.x; ay2 += v2.y;
        ax3 += v3.x; ay3 += v3.y;
    }
    for (; j < cnt; j++) {
        int s0 = __ldg(&g_csr_src[start + j]);
        float2 v = __half22float2(__ldg(&hw[(size_t)s0 * 32 + lane]));
        ax0 += v.x; ay0 += v.y;
    }

    float isqn = g_deg[node];
    float2 bb = ((const float2*)bias)[lane];
    float vx = fmaf(isqn, (ax0 + ax1) + (ax2 + ax3), bb.x);
    float vy = fmaf(isqn, (ay0 + ay1) + (ay2 + ay3), bb.y);

    float sum = vx + vy;
#pragma unroll
    for (int o = 16; o; o >>= 1) sum += __shfl_xor_sync(0xffffffffu, sum, o);
    float mu = sum * (1.0f / 64.0f);

    float dx = vx - mu, dy = vy - mu;
    float var = dx * dx + dy * dy;
#pragma unroll
    for (int o = 16; o; o >>= 1) var += __shfl_xor_sync(0xffffffffu, var, o);
    float rstd = rsqrtf(var * (1.0f / 64.0f) + 1e-5f);

    float2 gg = ((const float2*)lng)[lane];
    float2 lb = ((const float2*)lnb)[lane];
    float ox = fmaxf(fmaf(dx * rstd, gg.x, lb.x), 0.f);
    float oy = fmaxf(fmaf(dy * rstd, gg.y, lb.y), 0.f);

    if (!do_readout) {
        ((float2*)outh)[off] = make_float2(ox, oy);
    } else {
        float2 h1v = ((const float2*)g_h1)[off];
        float2 sk = make_float2(ox + h1v.x, oy + h1v.y);
        int grp = idx32 ? ((const int*)batch)[node]
                        : (int)((const long long*)batch)[node];
        atomicAdd(((float2*)g_readout) + (size_t)grp * 32 + lane, sk);
    }
}

// ---------------- post GEMM ----------------
__global__ void k_post(const float* __restrict__ W, const float* __restrict__ b,
                       float* __restrict__ out, int G) {
    __shared__ float r[64];
    int g = blockIdx.x;
    r[threadIdx.x] = g_readout[(size_t)g * 64 + threadIdx.x];
    __syncthreads();
    int c = threadIdx.x;
    if (c < 40) {
        float acc = b[c];
#pragma unroll
        for (int k = 0; k < 64; k++) acc = fmaf(r[k], __ldg(&W[k * 40 + c]), acc);
        out[(size_t)g * 40 + c] = acc;
    }
}

// ---------------- launch: pregemm(1), csr(2), gemm1(3), gather1(4) ... ----------------
extern "C" void kernel_launch(void* const* d_in, const int* in_sizes, int n_in,
                              void* d_out, int out_size) {
    const float* x      = (const float*)d_in[0];
    const void*  eidx   = d_in[1];
    const void*  batch  = d_in[2];
    const float* pre_w  = (const float*)d_in[3];
    const float* pre_b  = (const float*)d_in[4];
    const float* c1_w   = (const float*)d_in[5];
    const float* c1_b   = (const float*)d_in[6];
    const float* n1_g   = (const float*)d_in[7];
    const float* n1_b   = (const float*)d_in[8];
    const float* c2_w   = (const float*)d_in[9];
    const float* c2_b   = (const float*)d_in[10];
    const float* n2_g   = (const float*)d_in[11];
    const float* n2_b   = (const float*)d_in[12];
    const float* post_w = (const float*)d_in[13];
    const float* post_b = (const float*)d_in[14];

    int N = in_sizes[0] / 128;
    int E = in_sizes[1] / 2;
    int G = out_size / 40;

    float *p_h, *p_h1, *p_isq, *p_readout;
    __half* p_hws;
    int *p_cnt, *p_flag;
    cudaGetSymbolAddress((void**)&p_h,       g_h);
    cudaGetSymbolAddress((void**)&p_hws,     g_hws);
    cudaGetSymbolAddress((void**)&p_h1,      g_h1);
    cudaGetSymbolAddress((void**)&p_isq,     g_deg);
    cudaGetSymbolAddress((void**)&p_cnt,     g_cnt);
    cudaGetSymbolAddress((void**)&p_flag,    g_scanflag);
    cudaGetSymbolAddress((void**)&p_readout, g_readout);

    static cudaStream_t s1 = nullptr, s2 = nullptr;
    static cudaEvent_t evFork = nullptr, evS1 = nullptr, evS2 = nullptr;
    if (!s1) {
        cudaStreamCreateWithFlags(&s1, cudaStreamNonBlocking);
        cudaStreamCreateWithFlags(&s2, cudaStreamNonBlocking);
        cudaEventCreateWithFlags(&evFork, cudaEventDisableTiming);
        cudaEventCreateWithFlags(&evS1,   cudaEventDisableTiming);
        cudaEventCreateWithFlags(&evS2,   cudaEventDisableTiming);
    }

    cudaEventRecord(evFork, 0);
    cudaStreamWaitEvent(s1, evFork, 0);
    cudaStreamWaitEvent(s2, evFork, 0);

    // --- s1: pre-GEMM (kernel #1) ---
    k_gemm<128, 0><<<(N + 127) / 128, 128, 0, s1>>>(x, pre_w, pre_b, nullptr, p_h, N);
    cudaEventRecord(evS1, s1);

    // --- s2: memset nodes + fused CSR build (kernel #2), fully overlapped with pre-GEMM ---
    cudaMemsetAsync(p_cnt, 0, (size_t)N * 4, s2);
    cudaMemsetAsync(p_flag, 0, 128 * 4, s2);
    cudaMemsetAsync(p_readout, 0, (size_t)G * 64 * 4, s2);
    k_csr<<<148, 256, 0, s2>>>(eidx, E, N);
    cudaEventRecord(evS2, s2);

    // --- join on origin stream ---
    cudaStreamWaitEvent(0, evS1, 0);
    cudaStreamWaitEvent(0, evS2, 0);

    // layer 1 (kernels #3, #4)
    k_gemm<64, 1><<<(N + 127) / 128, 128>>>(p_h, c1_w, nullptr, p_isq, p_hws, N);
    k_gather<<<((size_t)N * 32 + 255) / 256, 256>>>(c1_b, n1_g, n1_b, p_h1, N, 0, nullptr, eidx, E);

    // layer 2 (kernels #5, #6)
    k_gemm<64, 1><<<(N + 127) / 128, 128>>>(p_h1, c2_w, nullptr, p_isq, p_hws, N);
    k_gather<<<((size_t)N * 32 + 255) / 256, 256>>>(c2_b, n2_g, n2_b, nullptr, N, 1, batch, eidx, E);

    // post (kernel #7)
    k_post<<<G, 64>>>(post_w, post_b, (float*)d_out, G);
}

// round 6
// speedup vs baseline: 1.0809x; 1.0809x over previous
#include <cuda_runtime.h>
#include <cuda_fp16.h>
#include <cstdint>
#include <cstddef>

// Problem constants: N=100000, E=1600000, F=128, H=64, C=40, G=2048
#define NMAX 100000
#define EMAX 1600000
#define GMAX 2048

// ---------------- scratch (device globals; no runtime alloc allowed) ----------------
__device__ __align__(16) float  g_h  [NMAX * 64];   // pre-MLP output (fp32)
__device__ __align__(16) __half g_hws[NMAX * 64];   // (h @ W) * isq (fp16) per layer
__device__ __align__(16) float  g_h1 [NMAX * 64];   // layer-1 activations (for skip)
__device__ __align__(16) float  g_deg[NMAX];        // isq
__device__ __align__(16) float  g_readout[GMAX * 64];
__device__ __align__(16) int    g_cnt[NMAX];        // per-dst degree
__device__ __align__(16) int    g_ptr[NMAX];        // CSR row starts
__device__ __align__(16) int    g_cursor[NMAX];     // fill cursors
__device__ __align__(16) int    g_csr_src[EMAX];    // CSR column (src) indices
__device__ int g_scanflag[128];                     // lookback published aggregates (+1)

// ---------------- per-block index-dtype detection ----------------
// Random src values in [0,N) read as int64 pairs give huge values -> detect int32.
__device__ __forceinline__ int block_detect_idx32(const void* e, int E, long long nlim,
                                                  int* s_flag) {
    if (threadIdx.x == 0) *s_flag = 0;
    __syncthreads();
    int m = E < 64 ? E : 64;
    if ((int)threadIdx.x < m) {
        long long v = ((const long long*)e)[threadIdx.x];
        if (v < 0 || v >= nlim) *s_flag = 1;
    }
    __syncthreads();
    return *s_flag;
}

// ---------------- degree histogram (4 edges/thread, full grid) ----------------
__global__ void __launch_bounds__(256) k_hist(const void* __restrict__ eidx, int E,
                                              long long nlim) {
    __shared__ int sf;
    int idx32 = block_detect_idx32(eidx, E, nlim, &sf);
    int base = (blockIdx.x * blockDim.x + threadIdx.x) * 4;
    if (idx32) {
        const int* d = (const int*)eidx + E;
#pragma unroll
        for (int k = 0; k < 4; k++) {
            int e = base + k;
            if (e < E) atomicAdd(&g_cnt[d[e]], 1);
        }
    } else {
        const long long* d = (const long long*)eidx + E;
#pragma unroll
        for (int k = 0; k < 4; k++) {
            int e = base + k;
            if (e < E) atomicAdd(&g_cnt[(int)d[e]], 1);
        }
    }
}

// ---------------- single-pass exclusive scan (lookback) + cursor + isq ----------------
// <=98 blocks, all resident in one wave -> spin-wait is deadlock-free.
__global__ void __launch_bounds__(256) k_scan(int n) {
    __shared__ int wsum[8];
    __shared__ int red[8];
    __shared__ int s_prefix;
    int bid = blockIdx.x;
    int base = bid * 1024 + threadIdx.x * 4;

    int c0 = 0, c1 = 0, c2 = 0, c3 = 0;
    if (base + 3 < n) {
        int4 c = *(const int4*)&g_cnt[base];
        c0 = c.x; c1 = c.y; c2 = c.z; c3 = c.w;
    } else if (base < n) {
        c0 = g_cnt[base];
        if (base + 1 < n) c1 = g_cnt[base + 1];
        if (base + 2 < n) c2 = g_cnt[base + 2];
    }
    int tot = c0 + c1 + c2 + c3;
    int lane = threadIdx.x & 31, wid = threadIdx.x >> 5;
    int v = tot;
#pragma unroll
    for (int o = 1; o < 32; o <<= 1) {
        int u = __shfl_up_sync(0xffffffffu, v, o);
        if (lane >= o) v += u;
    }
    if (lane == 31) wsum[wid] = v;
    __syncthreads();
    if (threadIdx.x == 0) {
        int s = 0;
        for (int i = 0; i < 8; i++) { int t = wsum[i]; wsum[i] = s; s += t; }
        atomicExch(&g_scanflag[bid], s + 1);   // publish aggregate (+1 = ready)
    }
    __syncthreads();

    int part = 0;
    if ((int)threadIdx.x < bid) {
        volatile int* f = &g_scanflag[threadIdx.x];
        int x;
        do { x = *f; } while (x == 0);
        part = x - 1;
    }
#pragma unroll
    for (int o = 16; o; o >>= 1) part += __shfl_xor_sync(0xffffffffu, part, o);
    if (lane == 0) red[wid] = part;
    __syncthreads();
    if (threadIdx.x == 0) {
        int s = 0;
        for (int i = 0; i < 8; i++) s += red[i];
        s_prefix = s;
    }
    __syncthreads();

    int excl = v - tot + wsum[wid] + s_prefix;
    if (base < n) {
        int p0 = excl, p1 = p0 + c0, p2 = p1 + c1, p3 = p2 + c2;
        g_ptr[base] = p0; g_cursor[base] = p0; g_deg[base] = rsqrtf((float)c0 + 1.0f);
        if (base + 1 < n) { g_ptr[base+1] = p1; g_cursor[base+1] = p1; g_deg[base+1] = rsqrtf((float)c1 + 1.0f); }
        if (base + 2 < n) { g_ptr[base+2] = p2; g_cursor[base+2] = p2; g_deg[base+2] = rsqrtf((float)c2 + 1.0f); }
        if (base + 3 < n) { g_ptr[base+3] = p3; g_cursor[base+3] = p3; g_deg[base+3] = rsqrtf((float)c3 + 1.0f); }
    }
}

// ---------------- CSR fill (4 edges/thread, full grid) ----------------
__global__ void __launch_bounds__(256) k_fill(const void* __restrict__ eidx, int E,
                                              long long nlim) {
    __shared__ int sf;
    int idx32 = block_detect_idx32(eidx, E, nlim, &sf);
    int base = (blockIdx.x * blockDim.x + threadIdx.x) * 4;
#pragma unroll
    for (int k = 0; k < 4; k++) {
        int e = base + k;
        if (e >= E) break;
        int src, dst;
        if (idx32) {
            const int* p = (const int*)eidx;
            src = p[e]; dst = p[E + e];
        } else {
            const long long* p = (const long long*)eidx;
            src = (int)p[e]; dst = (int)p[E + e];
        }
        int pos = atomicAdd(&g_cursor[dst], 1);
        g_csr_src[pos] = src;
    }
}

// ---------------- row GEMM, packed f32x2 FMA; fp32+bias OR fp16*(isq) output ---------
template<int K, int HALF_OUT>
__global__ void __launch_bounds__(128) k_gemm(const float* __restrict__ A,
                                              const float* __restrict__ W,
                                              const float* __restrict__ bias,
                                              const float* __restrict__ isq,
                                              void* __restrict__ out, int n) {
    __shared__ ulonglong2 Ws[K * 16];   // K rows x 64 floats, pre-packed f32x2 pairs
    __shared__ float      As[128 * 17];

    for (int i = threadIdx.x; i < K * 16; i += 128)
        Ws[i] = reinterpret_cast<const ulonglong2*>(W)[i];

    unsigned long long acc[32];
#pragma unroll
    for (int j = 0; j < 32; j++) acc[j] = 0ULL;

    int node = blockIdx.x * 128 + threadIdx.x;

    for (int k0 = 0; k0 < K; k0 += 16) {
        __syncthreads();
#pragma unroll
        for (int i = 0; i < 16; i++) {
            int idx = i * 128 + threadIdx.x;
            int nn = idx >> 4, kk = idx & 15;
            int gn = blockIdx.x * 128 + nn;
            As[nn * 17 + kk] = (gn < n) ? A[(size_t)gn * K + k0 + kk] : 0.f;
        }
        __syncthreads();
#pragma unroll
        for (int kk = 0; kk < 16; kk++) {
            float a = As[threadIdx.x * 17 + kk];
            unsigned long long a2;
            asm("mov.b64 %0, {%1, %1};" : "=l"(a2) : "f"(a));
            const ulonglong2* wr = &Ws[(k0 + kk) * 16];
#pragma unroll
            for (int j = 0; j < 16; j++) {
                ulonglong2 w = wr[j];
                asm("fma.rn.f32x2 %0, %1, %2, %0;" : "+l"(acc[2 * j])     : "l"(a2), "l"(w.x));
                asm("fma.rn.f32x2 %0, %1, %2, %0;" : "+l"(acc[2 * j + 1]) : "l"(a2), "l"(w.y));
            }
        }
    }

    if (node < n) {
        if (HALF_OUT) {
            float s = isq[node];
            __half2* o = reinterpret_cast<__half2*>(out) + (size_t)node * 32;
#pragma unroll
            for (int j = 0; j < 32; j++) {
                float lo, hi;
                asm("mov.b64 {%0, %1}, %2;" : "=f"(lo), "=f"(hi) : "l"(acc[j]));
                o[j] = __floats2half2_rn(lo * s, hi * s);
            }
        } else {
            float2* o = reinterpret_cast<float2*>(out) + (size_t)node * 32;
#pragma unroll
            for (int j = 0; j < 32; j++) {
                float lo, hi;
                asm("mov.b64 {%0, %1}, %2;" : "=f"(lo), "=f"(hi) : "l"(acc[j]));
                float2 b = reinterpret_cast<const float2*>(bias)[j];
                o[j] = make_float2(lo + b.x, hi + b.y);
            }
        }
    }
}

// ---------------- fused gather + self + bias + LN + ReLU (+skip+readout) -------------
// One warp per node; fp16 rows (one 128B line per neighbor); fp16 HADD2 accumulation
// in 4 independent accumulators (each sums ~cnt/4 values), fp32 final combine.
__global__ void __launch_bounds__(256) k_gather(const float* __restrict__ bias,
                                                const float* __restrict__ lng,
                                                const float* __restrict__ lnb,
                                                float* __restrict__ outh, int n,
                                                int do_readout,
                                                const void* __restrict__ batch,
                                                const void* __restrict__ eidx, int E) {
    __shared__ int sf;
    int idx32 = block_detect_idx32(eidx, E, (long long)n, &sf);

    int t = blockIdx.x * blockDim.x + threadIdx.x;
    int node = t >> 5, lane = t & 31;
    if (node >= n) return;

    int start = g_ptr[node];
    int cnt   = g_cnt[node];
    const __half2* hw = (const __half2*)g_hws;
    size_t off = (size_t)node * 32 + lane;

    __half2 h0 = __float2half2_rn(0.f);
    __half2 h1 = h0, h2 = h0, h3 = h0;

    int j = 0;
    for (; j + 3 < cnt; j += 4) {
        int s0 = __ldg(&g_csr_src[start + j]);
        int s1 = __ldg(&g_csr_src[start + j + 1]);
        int s2 = __ldg(&g_csr_src[start + j + 2]);
        int s3 = __ldg(&g_csr_src[start + j + 3]);
        __half2 v0 = __ldg(&hw[(size_t)s0 * 32 + lane]);
        __half2 v1 = __ldg(&hw[(size_t)s1 * 32 + lane]);
        __half2 v2 = __ldg(&hw[(size_t)s2 * 32 + lane]);
        __half2 v3 = __ldg(&hw[(size_t)s3 * 32 + lane]);
        h0 = __hadd2(h0, v0);
        h1 = __hadd2(h1, v1);
        h2 = __hadd2(h2, v2);
        h3 = __hadd2(h3, v3);
    }
    for (; j < cnt; j++) {
        int s0 = __ldg(&g_csr_src[start + j]);
        h0 = __hadd2(h0, __ldg(&hw[(size_t)s0 * 32 + lane]));
    }

    // fp32 final combine (+ self term, already isq-scaled)
    float2 f0 = __half22float2(h0);
    float2 f1 = __half22float2(h1);
    float2 f2 = __half22float2(h2);
    float2 f3 = __half22float2(h3);
    float2 self = __half22float2(__ldg(&hw[off]));
    float accx = ((f0.x + f1.x) + (f2.x + f3.x)) + self.x;
    float accy = ((f0.y + f1.y) + (f2.y + f3.y)) + self.y;

    float isqn = g_deg[node];
    float2 bb = ((const float2*)bias)[lane];
    float vx = fmaf(isqn, accx, bb.x);
    float vy = fmaf(isqn, accy, bb.y);

    float sum = vx + vy;
#pragma unroll
    for (int o = 16; o; o >>= 1) sum += __shfl_xor_sync(0xffffffffu, sum, o);
    float mu = sum * (1.0f / 64.0f);

    float dx = vx - mu, dy = vy - mu;
    float var = dx * dx + dy * dy;
#pragma unroll
    for (int o = 16; o; o >>= 1) var += __shfl_xor_sync(0xffffffffu, var, o);
    float rstd = rsqrtf(var * (1.0f / 64.0f) + 1e-5f);

    float2 gg = ((const float2*)lng)[lane];
    float2 lb = ((const float2*)lnb)[lane];
    float ox = fmaxf(fmaf(dx * rstd, gg.x, lb.x), 0.f);
    float oy = fmaxf(fmaf(dy * rstd, gg.y, lb.y), 0.f);

    if (!do_readout) {
        ((float2*)outh)[off] = make_float2(ox, oy);
    } else {
        float2 h1v = ((const float2*)g_h1)[off];
        float2 sk = make_float2(ox + h1v.x, oy + h1v.y);
        int grp = idx32 ? ((const int*)batch)[node]
                        : (int)((const long long*)batch)[node];
        atomicAdd(((float2*)g_readout) + (size_t)grp * 32 + lane, sk);
    }
}

// ---------------- post GEMM ----------------
__global__ void k_post(const float* __restrict__ W, const float* __restrict__ b,
                       float* __restrict__ out, int G) {
    __shared__ float r[64];
    int g = blockIdx.x;
    r[threadIdx.x] = g_readout[(size_t)g * 64 + threadIdx.x];
    __syncthreads();
    int c = threadIdx.x;
    if (c < 40) {
        float acc = b[c];
#pragma unroll
        for (int k = 0; k < 64; k++) acc = fmaf(r[k], __ldg(&W[k * 40 + c]), acc);
        out[(size_t)g * 40 + c] = acc;
    }
}

// ---------------- launch: pregemm(s1) || [hist,scan,fill](s2); join; layers ----------
extern "C" void kernel_launch(void* const* d_in, const int* in_sizes, int n_in,
                              void* d_out, int out_size) {
    const float* x      = (const float*)d_in[0];
    const void*  eidx   = d_in[1];
    const void*  batch  = d_in[2];
    const float* pre_w  = (const float*)d_in[3];
    const float* pre_b  = (const float*)d_in[4];
    const float* c1_w   = (const float*)d_in[5];
    const float* c1_b   = (const float*)d_in[6];
    const float* n1_g   = (const float*)d_in[7];
    const float* n1_b   = (const float*)d_in[8];
    const float* c2_w   = (const float*)d_in[9];
    const float* c2_b   = (const float*)d_in[10];
    const float* n2_g   = (const float*)d_in[11];
    const float* n2_b   = (const float*)d_in[12];
    const float* post_w = (const float*)d_in[13];
    const float* post_b = (const float*)d_in[14];

    int N = in_sizes[0] / 128;
    int E = in_sizes[1] / 2;
    int G = out_size / 40;

    float *p_h, *p_h1, *p_isq, *p_readout;
    __half* p_hws;
    int *p_cnt, *p_flag;
    cudaGetSymbolAddress((void**)&p_h,       g_h);
    cudaGetSymbolAddress((void**)&p_hws,     g_hws);
    cudaGetSymbolAddress((void**)&p_h1,      g_h1);
    cudaGetSymbolAddress((void**)&p_isq,     g_deg);
    cudaGetSymbolAddress((void**)&p_cnt,     g_cnt);
    cudaGetSymbolAddress((void**)&p_flag,    g_scanflag);
    cudaGetSymbolAddress((void**)&p_readout, g_readout);

    static cudaStream_t s1 = nullptr, s2 = nullptr;
    static cudaEvent_t evFork = nullptr, evS1 = nullptr, evS2 = nullptr;
    if (!s1) {
        cudaStreamCreateWithFlags(&s1, cudaStreamNonBlocking);
        cudaStreamCreateWithFlags(&s2, cudaStreamNonBlocking);
        cudaEventCreateWithFlags(&evFork, cudaEventDisableTiming);
        cudaEventCreateWithFlags(&evS1,   cudaEventDisableTiming);
        cudaEventCreateWithFlags(&evS2,   cudaEventDisableTiming);
    }

    cudaEventRecord(evFork, 0);
    cudaStreamWaitEvent(s1, evFork, 0);
    cudaStreamWaitEvent(s2, evFork, 0);

    // --- s1: pre-GEMM (kernel #1) ---
    k_gemm<128, 0><<<(N + 127) / 128, 128, 0, s1>>>(x, pre_w, pre_b, nullptr, p_h, N);
    cudaEventRecord(evS1, s1);

    // --- s2: memsets + CSR build (kernels #2-#4), overlapped with pre-GEMM ---
    cudaMemsetAsync(p_cnt, 0, (size_t)N * 4, s2);
    cudaMemsetAsync(p_flag, 0, 128 * 4, s2);
    cudaMemsetAsync(p_readout, 0, (size_t)G * 64 * 4, s2);
    k_hist<<<(E + 1023) / 1024, 256, 0, s2>>>(eidx, E, (long long)N);
    k_scan<<<(N + 1023) / 1024, 256, 0, s2>>>(N);
    k_fill<<<(E + 1023) / 1024, 256, 0, s2>>>(eidx, E, (long long)N);
    cudaEventRecord(evS2, s2);

    // --- join on origin stream ---
    cudaStreamWaitEvent(0, evS1, 0);
    cudaStreamWaitEvent(0, evS2, 0);

    // layer 1 (kernels #5, #6 -> ncu -s 5 captures gather1)
    k_gemm<64, 1><<<(N + 127) / 128, 128>>>(p_h, c1_w, nullptr, p_isq, p_hws, N);
    k_gather<<<((size_t)N * 32 + 255) / 256, 256>>>(c1_b, n1_g, n1_b, p_h1, N, 0, nullptr, eidx, E);

    // layer 2 (kernels #7, #8)
    k_gemm<64, 1><<<(N + 127) / 128, 128>>>(p_h1, c2_w, nullptr, p_isq, p_hws, N);
    k_gather<<<((size_t)N * 32 + 255) / 256, 256>>>(c2_b, n2_g, n2_b, nullptr, N, 1, batch, eidx, E);

    // post (kernel #9)
    k_post<<<G, 64>>>(post_w, post_b, (float*)d_out, G);
}

// round 7
// speedup vs baseline: 1.1737x; 1.0859x over previous
#include <cuda_runtime.h>
#include <cuda_fp16.h>
#include <cstdint>
#include <cstddef>

// Problem constants: N=100000, E=1600000, F=128, H=64, C=40, G=2048
#define NMAX 100000
#define EMAX 1600000
#define GMAX 2048

// ---------------- scratch (device globals; no runtime alloc allowed) ----------------
__device__ __align__(16) float  g_h  [NMAX * 64];   // pre-MLP output (fp32)
__device__ __align__(16) __half g_hws[NMAX * 64];   // (h @ W) * isq (fp16) per layer
__device__ __align__(16) float  g_h1 [NMAX * 64];   // layer-1 activations (for skip)
__device__ __align__(16) float  g_deg[NMAX];        // isq
__device__ __align__(16) float  g_readout[GMAX * 64];
__device__ __align__(16) int    g_cnt[NMAX];        // per-dst degree
__device__ __align__(16) int    g_ptr[NMAX];        // CSR row starts
__device__ __align__(16) int    g_cursor[NMAX];     // fill cursors
__device__ __align__(16) int    g_csr_src[EMAX];    // CSR column (src) indices
__device__ int g_scanflag[128];                     // lookback published aggregates (+1)
__device__ int g_idx32;                             // 1 if indices are int32

// ---------------- index dtype detection (one tiny kernel, capture-safe) --------------
__global__ void k_detect(const long long* e, int cnt, long long nlim) {
    int f = 0;
    int i = threadIdx.x;
    if (i < cnt) {
        long long v = e[i];
        f = (v < 0 || v >= nlim) ? 1 : 0;
    }
    int r = __syncthreads_or(f);
    if (threadIdx.x == 0) g_idx32 = r;
}

// ---------------- degree histogram (4 edges/thread, full grid) ----------------
__global__ void __launch_bounds__(256) k_hist(const void* __restrict__ eidx, int E) {
    int idx32 = g_idx32;
    int base = (blockIdx.x * blockDim.x + threadIdx.x) * 4;
    if (idx32) {
        const int* d = (const int*)eidx + E;
#pragma unroll
        for (int k = 0; k < 4; k++) {
            int e = base + k;
            if (e < E) atomicAdd(&g_cnt[d[e]], 1);
        }
    } else {
        const long long* d = (const long long*)eidx + E;
#pragma unroll
        for (int k = 0; k < 4; k++) {
            int e = base + k;
            if (e < E) atomicAdd(&g_cnt[(int)d[e]], 1);
        }
    }
}

// ---------------- single-pass exclusive scan (lookback) + cursor + isq ----------------
// <=98 blocks, all resident in one wave -> spin-wait is deadlock-free.
__global__ void __launch_bounds__(256) k_scan(int n) {
    __shared__ int wsum[8];
    __shared__ int red[8];
    __shared__ int s_prefix;
    int bid = blockIdx.x;
    int base = bid * 1024 + threadIdx.x * 4;

    int c0 = 0, c1 = 0, c2 = 0, c3 = 0;
    if (base + 3 < n) {
        int4 c = *(const int4*)&g_cnt[base];
        c0 = c.x; c1 = c.y; c2 = c.z; c3 = c.w;
    } else if (base < n) {
        c0 = g_cnt[base];
        if (base + 1 < n) c1 = g_cnt[base + 1];
        if (base + 2 < n) c2 = g_cnt[base + 2];
    }
    int tot = c0 + c1 + c2 + c3;
    int lane = threadIdx.x & 31, wid = threadIdx.x >> 5;
    int v = tot;
#pragma unroll
    for (int o = 1; o < 32; o <<= 1) {
        int u = __shfl_up_sync(0xffffffffu, v, o);
        if (lane >= o) v += u;
    }
    if (lane == 31) wsum[wid] = v;
    __syncthreads();
    if (threadIdx.x == 0) {
        int s = 0;
        for (int i = 0; i < 8; i++) { int t = wsum[i]; wsum[i] = s; s += t; }
        atomicExch(&g_scanflag[bid], s + 1);   // publish aggregate (+1 = ready)
    }
    __syncthreads();

    int part = 0;
    if ((int)threadIdx.x < bid) {
        volatile int* f = &g_scanflag[threadIdx.x];
        int x;
        do { x = *f; } while (x == 0);
        part = x - 1;
    }
#pragma unroll
    for (int o = 16; o; o >>= 1) part += __shfl_xor_sync(0xffffffffu, part, o);
    if (lane == 0) red[wid] = part;
    __syncthreads();
    if (threadIdx.x == 0) {
        int s = 0;
        for (int i = 0; i < 8; i++) s += red[i];
        s_prefix = s;
    }
    __syncthreads();

    int excl = v - tot + wsum[wid] + s_prefix;
    if (base < n) {
        int p0 = excl, p1 = p0 + c0, p2 = p1 + c1, p3 = p2 + c2;
        g_ptr[base] = p0; g_cursor[base] = p0; g_deg[base] = rsqrtf((float)c0 + 1.0f);
        if (base + 1 < n) { g_ptr[base+1] = p1; g_cursor[base+1] = p1; g_deg[base+1] = rsqrtf((float)c1 + 1.0f); }
        if (base + 2 < n) { g_ptr[base+2] = p2; g_cursor[base+2] = p2; g_deg[base+2] = rsqrtf((float)c2 + 1.0f); }
        if (base + 3 < n) { g_ptr[base+3] = p3; g_cursor[base+3] = p3; g_deg[base+3] = rsqrtf((float)c3 + 1.0f); }
    }
}

// ---------------- CSR fill (4 edges/thread, full grid) ----------------
__global__ void __launch_bounds__(256) k_fill(const void* __restrict__ eidx, int E) {
    int idx32 = g_idx32;
    int base = (blockIdx.x * blockDim.x + threadIdx.x) * 4;
#pragma unroll
    for (int k = 0; k < 4; k++) {
        int e = base + k;
        if (e >= E) break;
        int src, dst;
        if (idx32) {
            const int* p = (const int*)eidx;
            src = p[e]; dst = p[E + e];
        } else {
            const long long* p = (const long long*)eidx;
            src = (int)p[e]; dst = (int)p[E + e];
        }
        int pos = atomicAdd(&g_cursor[dst], 1);
        g_csr_src[pos] = src;
    }
}

// ---------------- row GEMM, packed f32x2 FMA; fp32+bias OR fp16*(isq) output ---------
template<int K, int HALF_OUT>
__global__ void __launch_bounds__(128) k_gemm(const float* __restrict__ A,
                                              const float* __restrict__ W,
                                              const float* __restrict__ bias,
                                              const float* __restrict__ isq,
                                              void* __restrict__ out, int n) {
    __shared__ ulonglong2 Ws[K * 16];   // K rows x 64 floats, pre-packed f32x2 pairs
    __shared__ float      As[128 * 17];

    for (int i = threadIdx.x; i < K * 16; i += 128)
        Ws[i] = reinterpret_cast<const ulonglong2*>(W)[i];

    unsigned long long acc[32];
#pragma unroll
    for (int j = 0; j < 32; j++) acc[j] = 0ULL;

    int node = blockIdx.x * 128 + threadIdx.x;

    for (int k0 = 0; k0 < K; k0 += 16) {
        __syncthreads();
#pragma unroll
        for (int i = 0; i < 16; i++) {
            int idx = i * 128 + threadIdx.x;
            int nn = idx >> 4, kk = idx & 15;
            int gn = blockIdx.x * 128 + nn;
            As[nn * 17 + kk] = (gn < n) ? A[(size_t)gn * K + k0 + kk] : 0.f;
        }
        __syncthreads();
#pragma unroll
        for (int kk = 0; kk < 16; kk++) {
            float a = As[threadIdx.x * 17 + kk];
            unsigned long long a2;
            asm("mov.b64 %0, {%1, %1};" : "=l"(a2) : "f"(a));
            const ulonglong2* wr = &Ws[(k0 + kk) * 16];
#pragma unroll
            for (int j = 0; j < 16; j++) {
                ulonglong2 w = wr[j];
                asm("fma.rn.f32x2 %0, %1, %2, %0;" : "+l"(acc[2 * j])     : "l"(a2), "l"(w.x));
                asm("fma.rn.f32x2 %0, %1, %2, %0;" : "+l"(acc[2 * j + 1]) : "l"(a2), "l"(w.y));
            }
        }
    }

    if (node < n) {
        if (HALF_OUT) {
            float s = isq[node];
            __half2* o = reinterpret_cast<__half2*>(out) + (size_t)node * 32;
#pragma unroll
            for (int j = 0; j < 32; j++) {
                float lo, hi;
                asm("mov.b64 {%0, %1}, %2;" : "=f"(lo), "=f"(hi) : "l"(acc[j]));
                o[j] = __floats2half2_rn(lo * s, hi * s);
            }
        } else {
            float2* o = reinterpret_cast<float2*>(out) + (size_t)node * 32;
#pragma unroll
            for (int j = 0; j < 32; j++) {
                float lo, hi;
                asm("mov.b64 {%0, %1}, %2;" : "=f"(lo), "=f"(hi) : "l"(acc[j]));
                float2 b = reinterpret_cast<const float2*>(bias)[j];
                o[j] = make_float2(lo + b.x, hi + b.y);
            }
        }
    }
}

// ---------------- fused gather + self + bias + LN + ReLU (+skip+readout) -------------
// One warp per node. CSR indices batch-loaded 32-at-a-time (coalesced, one LDG per
// 32 edges), distributed via shfl; 8-deep row-load pipelining; fp16 HADD2 accumulate.
__global__ void __launch_bounds__(256) k_gather(const float* __restrict__ bias,
                                                const float* __restrict__ lng,
                                                const float* __restrict__ lnb,
                                                float* __restrict__ outh, int n,
                                                int do_readout,
                                                const void* __restrict__ batch) {
    const unsigned FULL = 0xffffffffu;
    int t = blockIdx.x * blockDim.x + threadIdx.x;
    int node = t >> 5, lane = t & 31;
    if (node >= n) return;

    int start = g_ptr[node];
    int cnt   = g_cnt[node];
    const __half2* hw = (const __half2*)g_hws;
    size_t off = (size_t)node * 32 + lane;

    __half2 h0 = __float2half2_rn(0.f);
    __half2 h1 = h0, h2 = h0, h3 = h0;

    int done = 0;
    while (done < cnt) {
        int m = cnt - done;
        if (m > 32) m = 32;
        int bidx = 0;
        if (lane < m) bidx = __ldg(&g_csr_src[start + done + lane]);

        int j = 0;
        for (; j + 8 <= m; j += 8) {
            int s0 = __shfl_sync(FULL, bidx, j);
            int s1 = __shfl_sync(FULL, bidx, j + 1);
            int s2 = __shfl_sync(FULL, bidx, j + 2);
            int s3 = __shfl_sync(FULL, bidx, j + 3);
            int s4 = __shfl_sync(FULL, bidx, j + 4);
            int s5 = __shfl_sync(FULL, bidx, j + 5);
            int s6 = __shfl_sync(FULL, bidx, j + 6);
            int s7 = __shfl_sync(FULL, bidx, j + 7);
            __half2 v0 = __ldg(&hw[(size_t)s0 * 32 + lane]);
            __half2 v1 = __ldg(&hw[(size_t)s1 * 32 + lane]);
            __half2 v2 = __ldg(&hw[(size_t)s2 * 32 + lane]);
            __half2 v3 = __ldg(&hw[(size_t)s3 * 32 + lane]);
            __half2 v4 = __ldg(&hw[(size_t)s4 * 32 + lane]);
            __half2 v5 = __ldg(&hw[(size_t)s5 * 32 + lane]);
            __half2 v6 = __ldg(&hw[(size_t)s6 * 32 + lane]);
            __half2 v7 = __ldg(&hw[(size_t)s7 * 32 + lane]);
            h0 = __hadd2(h0, v0);
            h1 = __hadd2(h1, v1);
            h2 = __hadd2(h2, v2);
            h3 = __hadd2(h3, v3);
            h0 = __hadd2(h0, v4);
            h1 = __hadd2(h1, v5);
            h2 = __hadd2(h2, v6);
            h3 = __hadd2(h3, v7);
        }
        for (; j + 2 <= m; j += 2) {
            int s0 = __shfl_sync(FULL, bidx, j);
            int s1 = __shfl_sync(FULL, bidx, j + 1);
            __half2 v0 = __ldg(&hw[(size_t)s0 * 32 + lane]);
            __half2 v1 = __ldg(&hw[(size_t)s1 * 32 + lane]);
            h0 = __hadd2(h0, v0);
            h1 = __hadd2(h1, v1);
        }
        if (j < m) {
            int s0 = __shfl_sync(FULL, bidx, j);
            h0 = __hadd2(h0, __ldg(&hw[(size_t)s0 * 32 + lane]));
        }
        done += m;
    }

    // fp32 final combine (+ self term, already isq-scaled)
    float2 f0 = __half22float2(h0);
    float2 f1 = __half22float2(h1);
    float2 f2 = __half22float2(h2);
    float2 f3 = __half22float2(h3);
    float2 self = __half22float2(__ldg(&hw[off]));
    float accx = ((f0.x + f1.x) + (f2.x + f3.x)) + self.x;
    float accy = ((f0.y + f1.y) + (f2.y + f3.y)) + self.y;

    float isqn = g_deg[node];
    float2 bb = ((const float2*)bias)[lane];
    float vx = fmaf(isqn, accx, bb.x);
    float vy = fmaf(isqn, accy, bb.y);

    float sum = vx + vy;
#pragma unroll
    for (int o = 16; o; o >>= 1) sum += __shfl_xor_sync(FULL, sum, o);
    float mu = sum * (1.0f / 64.0f);

    float dx = vx - mu, dy = vy - mu;
    float var = dx * dx + dy * dy;
#pragma unroll
    for (int o = 16; o; o >>= 1) var += __shfl_xor_sync(FULL, var, o);
    float rstd = rsqrtf(var * (1.0f / 64.0f) + 1e-5f);

    float2 gg = ((const float2*)lng)[lane];
    float2 lb = ((const float2*)lnb)[lane];
    float ox = fmaxf(fmaf(dx * rstd, gg.x, lb.x), 0.f);
    float oy = fmaxf(fmaf(dy * rstd, gg.y, lb.y), 0.f);

    if (!do_readout) {
        ((float2*)outh)[off] = make_float2(ox, oy);
    } else {
        float2 h1v = ((const float2*)g_h1)[off];
        float2 sk = make_float2(ox + h1v.x, oy + h1v.y);
        int grp = g_idx32 ? ((const int*)batch)[node]
                          : (int)((const long long*)batch)[node];
        atomicAdd(((float2*)g_readout) + (size_t)grp * 32 + lane, sk);
    }
}

// ---------------- post GEMM ----------------
__global__ void k_post(const float* __restrict__ W, const float* __restrict__ b,
                       float* __restrict__ out, int G) {
    __shared__ float r[64];
    int g = blockIdx.x;
    r[threadIdx.x] = g_readout[(size_t)g * 64 + threadIdx.x];
    __syncthreads();
    int c = threadIdx.x;
    if (c < 40) {
        float acc = b[c];
#pragma unroll
        for (int k = 0; k < 64; k++) acc = fmaf(r[k], __ldg(&W[k * 40 + c]), acc);
        out[(size_t)g * 40 + c] = acc;
    }
}

// ---------------- launch: fine-grained fork/join ----------------
extern "C" void kernel_launch(void* const* d_in, const int* in_sizes, int n_in,
                              void* d_out, int out_size) {
    const float* x      = (const float*)d_in[0];
    const void*  eidx   = d_in[1];
    const void*  batch  = d_in[2];
    const float* pre_w  = (const float*)d_in[3];
    const float* pre_b  = (const float*)d_in[4];
    const float* c1_w   = (const float*)d_in[5];
    const float* c1_b   = (const float*)d_in[6];
    const float* n1_g   = (const float*)d_in[7];
    const float* n1_b   = (const float*)d_in[8];
    const float* c2_w   = (const float*)d_in[9];
    const float* c2_b   = (const float*)d_in[10];
    const float* n2_g   = (const float*)d_in[11];
    const float* n2_b   = (const float*)d_in[12];
    const float* post_w = (const float*)d_in[13];
    const float* post_b = (const float*)d_in[14];

    int N = in_sizes[0] / 128;
    int E = in_sizes[1] / 2;
    int G = out_size / 40;

    float *p_h, *p_h1, *p_isq, *p_readout;
    __half* p_hws;
    int *p_cnt, *p_flag;
    cudaGetSymbolAddress((void**)&p_h,       g_h);
    cudaGetSymbolAddress((void**)&p_hws,     g_hws);
    cudaGetSymbolAddress((void**)&p_h1,      g_h1);
    cudaGetSymbolAddress((void**)&p_isq,     g_deg);
    cudaGetSymbolAddress((void**)&p_cnt,     g_cnt);
    cudaGetSymbolAddress((void**)&p_flag,    g_scanflag);
    cudaGetSymbolAddress((void**)&p_readout, g_readout);

    static cudaStream_t s1 = nullptr, s2 = nullptr;
    static cudaEvent_t evFork = nullptr, evIsq = nullptr, evG1 = nullptr, evCsr = nullptr;
    if (!s1) {
        cudaStreamCreateWithFlags(&s1, cudaStreamNonBlocking);
        cudaStreamCreateWithFlags(&s2, cudaStreamNonBlocking);
        cudaEventCreateWithFlags(&evFork, cudaEventDisableTiming);
        cudaEventCreateWithFlags(&evIsq,  cudaEventDisableTiming);
        cudaEventCreateWithFlags(&evG1,   cudaEventDisableTiming);
        cudaEventCreateWithFlags(&evCsr,  cudaEventDisableTiming);
    }

    cudaEventRecord(evFork, 0);
    cudaStreamWaitEvent(s1, evFork, 0);
    cudaStreamWaitEvent(s2, evFork, 0);

    // --- s2: detect + memsets + CSR build ---
    int dcnt = 2 * E < 256 ? 2 * E : 256;
    k_detect<<<1, 256, 0, s2>>>((const long long*)eidx, dcnt, (long long)N);
    cudaMemsetAsync(p_cnt, 0, (size_t)N * 4, s2);
    cudaMemsetAsync(p_flag, 0, 128 * 4, s2);
    cudaMemsetAsync(p_readout, 0, (size_t)G * 64 * 4, s2);
    k_hist<<<(E + 1023) / 1024, 256, 0, s2>>>(eidx, E);
    k_scan<<<(N + 1023) / 1024, 256, 0, s2>>>(N);   // produces isq + ptr + cursor
    cudaEventRecord(evIsq, s2);
    k_fill<<<(E + 1023) / 1024, 256, 0, s2>>>(eidx, E);
    cudaEventRecord(evCsr, s2);

    // --- s1: pre-GEMM, then gemm1 (needs only isq) — overlaps with k_fill ---
    k_gemm<128, 0><<<(N + 127) / 128, 128, 0, s1>>>(x, pre_w, pre_b, nullptr, p_h, N);
    cudaStreamWaitEvent(s1, evIsq, 0);
    k_gemm<64, 1><<<(N + 127) / 128, 128, 0, s1>>>(p_h, c1_w, nullptr, p_isq, p_hws, N);
    cudaEventRecord(evG1, s1);

    // --- join on origin stream ---
    cudaStreamWaitEvent(0, evG1, 0);
    cudaStreamWaitEvent(0, evCsr, 0);

    // layer 1 gather -> h1
    k_gather<<<((size_t)N * 32 + 255) / 256, 256>>>(c1_b, n1_g, n1_b, p_h1, N, 0, nullptr);

    // layer 2
    k_gemm<64, 1><<<(N + 127) / 128, 128>>>(p_h1, c2_w, nullptr, p_isq, p_hws, N);
    k_gather<<<((size_t)N * 32 + 255) / 256, 256>>>(c2_b, n2_g, n2_b, nullptr, N, 1, batch);

    // post
    k_post<<<G, 64>>>(post_w, post_b, (float*)d_out, G);
}